// round 15
// baseline (speedup 1.0000x reference)
#include <cuda_runtime.h>

#define NTHR 256
#define NEWTON 8
typedef unsigned int u32;
typedef unsigned long long u64;

#define BUF_W 9216               // one buffer (K:128x36x2pl / Vt:64x68x2pl)
#define Q_W   (2 * BUF_W)        // Q staging overlays buf2 (dead after hoist)
#define RED_W (2 * BUF_W)        // Newton reduction overlays buf2
#define O_W   0                  // O overlays buf0 (zeroed at last chunk)
#define TOT_W (3 * BUF_W)        // 27648
#define SMEM_BYTES (TOT_W * 4)   // 110592

__device__ uint4 g_QH[524288], g_QL[524288];
__device__ uint4 g_KH[524288], g_KL[524288];
__device__ uint4 g_VTH[524288], g_VTL[524288];

__device__ __forceinline__ u32 cvt2(float hi, float lo) {
    u32 d; asm("cvt.rn.bf16x2.f32 %0, %1, %2;" : "=r"(d) : "f"(hi), "f"(lo)); return d;
}
__device__ __forceinline__ u64 pk64(float lo, float hi) {
    u64 d; asm("mov.b64 %0, {%1, %2};" : "=l"(d) : "f"(lo), "f"(hi)); return d;
}
__device__ __forceinline__ u64 dup2(float v) {
    u64 d; asm("mov.b64 %0, {%1, %1};" : "=l"(d) : "f"(v)); return d;
}
__device__ __forceinline__ u64 add2(u64 a, u64 b) {
    u64 d; asm("add.rn.f32x2 %0, %1, %2;" : "=l"(d) : "l"(a), "l"(b)); return d;
}
__device__ __forceinline__ u64 mul2(u64 a, u64 b) {
    u64 d; asm("mul.rn.f32x2 %0, %1, %2;" : "=l"(d) : "l"(a), "l"(b)); return d;
}
__device__ __forceinline__ u64 fma2(u64 a, u64 b, u64 c) {
    u64 d; asm("fma.rn.f32x2 %0, %1, %2, %3;" : "=l"(d) : "l"(a), "l"(b), "l"(c)); return d;
}
__device__ __forceinline__ void mma16816(float* c, const u32* a, u32 b0, u32 b1) {
    asm volatile("mma.sync.aligned.m16n8k16.row.col.f32.bf16.bf16.f32 "
        "{%0,%1,%2,%3}, {%4,%5,%6,%7}, {%8,%9}, {%0,%1,%2,%3};"
        : "+f"(c[0]), "+f"(c[1]), "+f"(c[2]), "+f"(c[3])
        : "r"(a[0]), "r"(a[1]), "r"(a[2]), "r"(a[3]), "r"(b0), "r"(b1));
}
__device__ __forceinline__ void ldmx4(u32 addr, u32* r) {
    asm volatile("ldmatrix.sync.aligned.m8n8.x4.shared.b16 {%0,%1,%2,%3}, [%4];"
        : "=r"(r[0]), "=r"(r[1]), "=r"(r[2]), "=r"(r[3]) : "r"(addr));
}
__device__ __forceinline__ u32 s2u(const void* p) {
    u32 a;
    asm("{ .reg .u64 t; cvta.to.shared.u64 t, %1; cvt.u32.u64 %0, t; }" : "=r"(a) : "l"(p));
    return a;
}
__device__ __forceinline__ void cp16(u32 dst, const void* src) {
    asm volatile("cp.async.ca.shared.global [%0], [%1], 16;"
                 :: "r"(dst), "l"(__cvta_generic_to_global(src)));
}
#define CP_COMMIT() asm volatile("cp.async.commit_group;" ::: "memory")
#define CP_WAIT(n)  asm volatile("cp.async.wait_group " #n ";" ::: "memory")

__global__ void __launch_bounds__(512) prepQK(const float4* __restrict__ q,
                                              const float4* __restrict__ k)
{
    int i = blockIdx.x * 512 + threadIdx.x;
    float4 f = q[i];
    f.x *= 0.0625f; f.y *= 0.0625f; f.z *= 0.0625f; f.w *= 0.0625f;
    u32 h0 = cvt2(f.y, f.x), h1 = cvt2(f.w, f.z);
    u32 l0 = cvt2(f.y - __uint_as_float(h0 & 0xffff0000u),
                  f.x - __uint_as_float(h0 << 16));
    u32 l1 = cvt2(f.w - __uint_as_float(h1 & 0xffff0000u),
                  f.z - __uint_as_float(h1 << 16));
    ((uint2*)g_QH)[i] = make_uint2(h0, h1);
    ((uint2*)g_QL)[i] = make_uint2(l0, l1);
    f = k[i];
    h0 = cvt2(f.y, f.x); h1 = cvt2(f.w, f.z);
    l0 = cvt2(f.y - __uint_as_float(h0 & 0xffff0000u),
              f.x - __uint_as_float(h0 << 16));
    l1 = cvt2(f.w - __uint_as_float(h1 & 0xffff0000u),
              f.z - __uint_as_float(h1 << 16));
    ((uint2*)g_KH)[i] = make_uint2(h0, h1);
    ((uint2*)g_KL)[i] = make_uint2(l0, l1);
}

__global__ void __launch_bounds__(256) prepV(const float* __restrict__ v)
{
    int bh = blockIdx.x, kb = blockIdx.y;
    int d = threadIdx.x & 63, kg = threadIdx.x >> 6;
    const float* Vb = v + bh * 65536;
#pragma unroll
    for (int c = 0; c < 4; c++) {
        int k0 = kb * 128 + c * 32 + kg * 8;
        float x[8];
#pragma unroll
        for (int j = 0; j < 8; j++) x[j] = Vb[(k0 + j) * 64 + d] * 0.25f;
        u32 h[4], l[4];
#pragma unroll
        for (int p = 0; p < 4; p++) {
            h[p] = cvt2(x[2*p+1], x[2*p]);
            l[p] = cvt2(x[2*p+1] - __uint_as_float(h[p] & 0xffff0000u),
                        x[2*p]   - __uint_as_float(h[p] << 16));
        }
        int base = bh * 8192 + d * 128 + (k0 >> 3);
        g_VTH[base] = make_uint4(h[0], h[1], h[2], h[3]);
        g_VTL[base] = make_uint4(l[0], l[1], l[2], l[3]);
    }
}

__global__ void __launch_bounds__(NTHR, 2)
attn_regP(float* __restrict__ og)
{
    extern __shared__ u32 sm[];
    float* smf = (float*)sm;
    const int tid  = threadIdx.x;
    const int lane = tid & 31;
    const int wid  = tid >> 5;
    const int g    = lane >> 2;
    const int tq   = lane & 3;
    const int qt   = blockIdx.x;
    const int bh   = blockIdx.y;
    float* Og = og + (size_t)bh * 65536 + (size_t)qt * 1024;
    const u32 smb = s2u(sm);

    // ---- prologue: group0 = {Q, K0}, group1 = {K1} ----
    {
        int pl = tid >> 7, rem = tid & 127, row = rem >> 3, seg = rem & 7;
        cp16(smb + (Q_W + pl * 576 + row * 36 + seg * 4) * 4,
             (pl ? g_QL : g_QH) + (size_t)bh * 8192 + (qt * 16 + row) * 8 + seg);
    }
#pragma unroll
    for (int i = 0; i < 4; i++) {
        int idx = i * NTHR + tid, row = idx >> 3, seg = idx & 7;
        int gi = bh * 8192 + row * 8 + seg;
        cp16(smb + (row * 36 + seg * 4) * 4, g_KH + gi);
        cp16(smb + (4608 + row * 36 + seg * 4) * 4, g_KL + gi);
    }
    CP_COMMIT();
#pragma unroll
    for (int i = 0; i < 4; i++) {
        int idx = i * NTHR + tid, row = idx >> 3, seg = idx & 7;
        int gi = bh * 8192 + (128 + row) * 8 + seg;
        cp16(smb + (BUF_W + row * 36 + seg * 4) * 4, g_KH + gi);
        cp16(smb + (BUF_W + 4608 + row * 36 + seg * 4) * 4, g_KL + gi);
    }
    CP_COMMIT();
    CP_WAIT(1);
    __syncthreads();

    // ---- hoist Q fragments ----
    const u32 QHB = smb + Q_W * 4, QLB = QHB + 2304;
    const int aAdr = (lane & 15) * 144 + (lane >> 4) * 16;
    u32 qh[4][4], ql[4][4];
#pragma unroll
    for (int ks = 0; ks < 4; ks++) {
        ldmx4(QHB + aAdr + ks * 32, qh[ks]);
        ldmx4(QLB + aAdr + ks * 32, ql[ks]);
    }
    __syncthreads();   // Q dead; buf2 may now be prefetched into

    // ===== GEMM1: 8 chunks, 3-stage pipeline, 1 sync/chunk =====
    // B-frag ldmx4: 4 mats = (tile tl, k-half) pairs
    const int bm = lane >> 3, br = lane & 7;
    const int bAdr0 = (16 * wid + (bm >> 1) * 8 + br) * 144 + (bm & 1) * 16;

    float cc[16][4];
#pragma unroll 1
    for (int c = 0; c < 8; c++) {
        if (c) {
            if (c < 7) { CP_WAIT(1); } else { CP_WAIT(0); }
            __syncthreads();
        }
        if (c < 6) {
            const int nb = (c + 2) % 3;
#pragma unroll
            for (int i = 0; i < 4; i++) {
                int idx = i * NTHR + tid, row = idx >> 3, seg = idx & 7;
                int gi = bh * 8192 + ((c + 2) * 128 + row) * 8 + seg;
                cp16(smb + (nb * BUF_W + row * 36 + seg * 4) * 4, g_KH + gi);
                cp16(smb + (nb * BUF_W + 4608 + row * 36 + seg * 4) * 4, g_KL + gi);
            }
            CP_COMMIT();
        }
        const u32 KHB = smb + (c % 3) * (BUF_W * 4);
        float* c0 = cc[2 * c];
        float* c1 = cc[2 * c + 1];
        c0[0] = c0[1] = c0[2] = c0[3] = 0.f;
        c1[0] = c1[1] = c1[2] = c1[3] = 0.f;
#pragma unroll
        for (int ks = 0; ks < 4; ks++) {
            u32 Bh[4], Bl[4];
            ldmx4(KHB + bAdr0 + ks * 32, Bh);
            ldmx4(KHB + 18432 + bAdr0 + ks * 32, Bl);
            mma16816(c0, qh[ks], Bh[0], Bh[1]);
            mma16816(c0, qh[ks], Bl[0], Bl[1]);
            mma16816(c0, ql[ks], Bh[0], Bh[1]);
            mma16816(c1, qh[ks], Bh[2], Bh[3]);
            mma16816(c1, qh[ks], Bl[2], Bl[3]);
            mma16816(c1, ql[ks], Bh[2], Bh[3]);
        }
    }

    // ---- V0 -> buf0 (buf0 free: all warps past c=7 top sync) ----
#pragma unroll
    for (int i = 0; i < 4; i++) {
        int idx = i * NTHR + tid, d = idx >> 4, s = idx & 15;
        int gi = bh * 8192 + d * 128 + s;
        cp16(smb + (d * 68 + s * 4) * 4, g_VTH + gi);
        cp16(smb + (4608 + d * 68 + s * 4) * 4, g_VTL + gi);
    }
    CP_COMMIT();
    __syncthreads();   // K7 compute done everywhere -> buf1 free
#pragma unroll
    for (int i = 0; i < 4; i++) {
        int idx = i * NTHR + tid, d = idx >> 4, s = idx & 15;
        int gi = bh * 8192 + d * 128 + 16 + s;
        cp16(smb + (BUF_W + d * 68 + s * 4) * 4, g_VTH + gi);
        cp16(smb + (BUF_W + 4608 + d * 68 + s * 4) * 4, g_VTL + gi);
    }
    CP_COMMIT();

    // ===== entmax-1.5 Newton in registers (rows g, g+8); RED in buf2 =====
    float mg = -1e30f, mh = -1e30f;
#pragma unroll
    for (int T = 0; T < 16; T++) {
        mg = fmaxf(mg, fmaxf(cc[T][0], cc[T][1]));
        mh = fmaxf(mh, fmaxf(cc[T][2], cc[T][3]));
    }
    mg = fmaxf(mg, __shfl_xor_sync(~0u, mg, 1));
    mg = fmaxf(mg, __shfl_xor_sync(~0u, mg, 2));
    mh = fmaxf(mh, __shfl_xor_sync(~0u, mh, 1));
    mh = fmaxf(mh, __shfl_xor_sync(~0u, mh, 2));
    if (tq == 0) {
        smf[RED_W + (32 + g) * 8 + wid] = mg;
        smf[RED_W + (40 + g) * 8 + wid] = mh;
    }
    __syncthreads();
    float Mg = -1e30f, Mh = -1e30f;
#pragma unroll
    for (int w = 0; w < 8; w++) {
        Mg = fmaxf(Mg, smf[RED_W + (32 + g) * 8 + w]);
        Mh = fmaxf(Mh, smf[RED_W + (40 + g) * 8 + w]);
    }
    float taug = Mg - 1.f, tauh = Mh - 1.f;

    u64 xg[16], xh[16];
#pragma unroll
    for (int T = 0; T < 16; T++) {
        xg[T] = pk64(cc[T][0], cc[T][1]);
        xh[T] = pk64(cc[T][2], cc[T][3]);
    }
    const u64 ABS2 = 0x7fffffff7fffffffULL;
#pragma unroll 1
    for (int it = 0; it < NEWTON; it++) {
        const int p = it & 1;
        u64 ntg = dup2(-taug), nth = dup2(-tauh);
        u64 s2g = 0, r2g = 0, s2h = 0, r2h = 0;
#pragma unroll
        for (int T = 0; T < 16; T++) {
            u64 tg = add2(xg[T], ntg);
            u64 ug = add2(tg, tg & ABS2);        // 2*max(t,0)
            s2g = fma2(ug, ug, s2g); r2g = add2(r2g, ug);
            u64 th = add2(xh[T], nth);
            u64 uh = add2(th, th & ABS2);
            s2h = fma2(uh, uh, s2h); r2h = add2(r2h, uh);
        }
        float2 v2;
        v2 = *(float2*)&s2g; float fsg = v2.x + v2.y;
        v2 = *(float2*)&r2g; float frg = v2.x + v2.y;
        v2 = *(float2*)&s2h; float fsh = v2.x + v2.y;
        v2 = *(float2*)&r2h; float frh = v2.x + v2.y;
        fsg += __shfl_xor_sync(~0u, fsg, 1); fsg += __shfl_xor_sync(~0u, fsg, 2);
        frg += __shfl_xor_sync(~0u, frg, 1); frg += __shfl_xor_sync(~0u, frg, 2);
        fsh += __shfl_xor_sync(~0u, fsh, 1); fsh += __shfl_xor_sync(~0u, fsh, 2);
        frh += __shfl_xor_sync(~0u, frh, 1); frh += __shfl_xor_sync(~0u, frh, 2);
        if (tq == 0) {
            smf[RED_W + (p * 32 + g) * 8 + wid]      = fsg;
            smf[RED_W + (p * 32 + 16 + g) * 8 + wid] = frg;
            smf[RED_W + (p * 32 + 8 + g) * 8 + wid]  = fsh;
            smf[RED_W + (p * 32 + 24 + g) * 8 + wid] = frh;
        }
        __syncthreads();
        float S = 0.f, R = 0.f, Sh = 0.f, Rh = 0.f;
#pragma unroll
        for (int w = 0; w < 8; w++) {
            S  += smf[RED_W + (p * 32 + g) * 8 + w];
            R  += smf[RED_W + (p * 32 + 16 + g) * 8 + w];
            Sh += smf[RED_W + (p * 32 + 8 + g) * 8 + w];
            Rh += smf[RED_W + (p * 32 + 24 + g) * 8 + w];
        }
        taug += __fdividef(S - 4.f, 4.f * R);
        tauh += __fdividef(Sh - 4.f, 4.f * Rh);
    }
    const u64 ntgF = dup2(-taug), nthF = dup2(-tauh);

    // ===== GEMM2: 8 chunks, 3-stage pipeline, fused m16n8k16 =====
    float oc[8][4];
#pragma unroll
    for (int dt = 0; dt < 8; dt++)
        oc[dt][0] = oc[dt][1] = oc[dt][2] = oc[dt][3] = 0.f;

#pragma unroll 1
    for (int c = 0; c < 8; c++) {
        if (c < 7) { CP_WAIT(1); } else { CP_WAIT(0); }
        __syncthreads();
        if (c < 6) {
            const int nb = (c + 2) % 3;
#pragma unroll
            for (int i = 0; i < 4; i++) {
                int idx = i * NTHR + tid, d = idx >> 4, s = idx & 15;
                int gi = bh * 8192 + d * 128 + (c + 2) * 16 + s;
                cp16(smb + (nb * BUF_W + d * 68 + s * 4) * 4, g_VTH + gi);
                cp16(smb + (nb * BUF_W + 4608 + d * 68 + s * 4) * 4, g_VTL + gi);
            }
            CP_COMMIT();
        }
        if (c == 7) {   // buf0 dead (last read at c=6); zero O overlay
            for (int i = tid; i < 16 * 68; i += NTHR) smf[O_W + i] = 0.f;
            __syncthreads();
        }
        const u32 VHB = smb + (c % 3) * (BUF_W * 4);

        // A-frags for both k8 halves straight from registers
        u32 aH[4], aL[4];
#pragma unroll
        for (int kk = 0; kk < 2; kk++) {
            const int T = 2 * c + kk;
            u64 tg = add2(xg[T], ntgF);
            u64 ug = add2(tg, tg & ABS2);
            u64 Pg = mul2(ug, ug);
            u64 th = add2(xh[T], nthF);
            u64 uh = add2(th, th & ABS2);
            u64 Ph = mul2(uh, uh);
            float2 pg = *(float2*)&Pg, ph = *(float2*)&Ph;
            u32 h0 = cvt2(pg.y, pg.x);
            u32 h1 = cvt2(ph.y, ph.x);
            aH[2 * kk]     = h0;
            aH[2 * kk + 1] = h1;
            aL[2 * kk]     = cvt2(pg.y - __uint_as_float(h0 & 0xffff0000u),
                                  pg.x - __uint_as_float(h0 << 16));
            aL[2 * kk + 1] = cvt2(ph.y - __uint_as_float(h1 & 0xffff0000u),
                                  ph.x - __uint_as_float(h1 << 16));
        }

        const u32 vA0 = VHB + lane * 272 + (16 * wid) * 2;   // k half 0
        const u32 vA1 = vA0 + 16;                            // k half 1
        u32 X0[4], X1[4], Z0[4], Z1[4];
        ldmx4(vA0, X0);            // hi, d 0-31
        ldmx4(vA1, X1);
        ldmx4(vA0 + 18432, Z0);    // lo, d 0-31
        ldmx4(vA1 + 18432, Z1);
#pragma unroll
        for (int dt = 0; dt < 4; dt++) {
            mma16816(oc[dt], aH, X0[dt], X1[dt]);
            mma16816(oc[dt], aH, Z0[dt], Z1[dt]);
            mma16816(oc[dt], aL, X0[dt], X1[dt]);
        }
        ldmx4(vA0 + 8704, X0);             // hi, d 32-63
        ldmx4(vA1 + 8704, X1);
        ldmx4(vA0 + 8704 + 18432, Z0);     // lo, d 32-63
        ldmx4(vA1 + 8704 + 18432, Z1);
#pragma unroll
        for (int dt = 0; dt < 4; dt++) {
            mma16816(oc[dt + 4], aH, X0[dt], X1[dt]);
            mma16816(oc[dt + 4], aH, Z0[dt], Z1[dt]);
            mma16816(oc[dt + 4], aL, X0[dt], X1[dt]);
        }
    }

    // ===== k-split reduction + output =====
#pragma unroll
    for (int dt = 0; dt < 8; dt++) {
        int col = dt * 8 + 2 * tq;
        atomicAdd(&smf[O_W + g * 68 + col],           oc[dt][0]);
        atomicAdd(&smf[O_W + g * 68 + col + 1],       oc[dt][1]);
        atomicAdd(&smf[O_W + (g + 8) * 68 + col],     oc[dt][2]);
        atomicAdd(&smf[O_W + (g + 8) * 68 + col + 1], oc[dt][3]);
    }
    __syncthreads();
#pragma unroll
    for (int i = 0; i < 4; i++) {
        int idx = i * NTHR + tid;
        int q = idx >> 6, d = idx & 63;
        Og[idx] = smf[O_W + q * 68 + d];
    }
}

extern "C" void kernel_launch(void* const* d_in, const int* in_sizes, int n_in,
                              void* d_out, int out_size)
{
    const float* q = (const float*)d_in[0];
    const float* k = (const float*)d_in[1];
    const float* v = (const float*)d_in[2];
    float* out = (float*)d_out;

    cudaFuncSetAttribute(attn_regP,
                         cudaFuncAttributeMaxDynamicSharedMemorySize, SMEM_BYTES);

    prepQK<<<2048, 512>>>((const float4*)q, (const float4*)k);
    prepV<<<dim3(64, 8), 256>>>(v);
    dim3 grid(64, 64);
    attn_regP<<<grid, NTHR, SMEM_BYTES>>>(out);
}

// round 16
// speedup vs baseline: 1.0917x; 1.0917x over previous
#include <cuda_runtime.h>

#define NTHR 256
#define NEWTON 8
typedef unsigned int u32;
typedef unsigned long long u64;

#define Q_W    0          // 2 planes x 16 x 36 w
#define K_W    1152       // 2 buf x 9216 w (K 128x36x2pl / Vt 64x68x2pl)
#define O_W    19584      // 16 x 68 f32
#define RED_W  20672      // 512 w reduction slots
#define TOT_W  21184
#define SMEM_BYTES (TOT_W * 4)   // 84736

__device__ uint4 g_QH[524288], g_QL[524288];
__device__ uint4 g_KH[524288], g_KL[524288];
__device__ uint4 g_VTH[524288], g_VTL[524288];

__device__ __forceinline__ u32 cvt2(float hi, float lo) {
    u32 d; asm("cvt.rn.bf16x2.f32 %0, %1, %2;" : "=r"(d) : "f"(hi), "f"(lo)); return d;
}
__device__ __forceinline__ u64 pk64(float lo, float hi) {
    u64 d; asm("mov.b64 %0, {%1, %2};" : "=l"(d) : "f"(lo), "f"(hi)); return d;
}
__device__ __forceinline__ u64 dup2(float v) {
    u64 d; asm("mov.b64 %0, {%1, %1};" : "=l"(d) : "f"(v)); return d;
}
__device__ __forceinline__ u64 add2(u64 a, u64 b) {
    u64 d; asm("add.rn.f32x2 %0, %1, %2;" : "=l"(d) : "l"(a), "l"(b)); return d;
}
__device__ __forceinline__ u64 mul2(u64 a, u64 b) {
    u64 d; asm("mul.rn.f32x2 %0, %1, %2;" : "=l"(d) : "l"(a), "l"(b)); return d;
}
__device__ __forceinline__ u64 fma2(u64 a, u64 b, u64 c) {
    u64 d; asm("fma.rn.f32x2 %0, %1, %2, %3;" : "=l"(d) : "l"(a), "l"(b), "l"(c)); return d;
}
__device__ __forceinline__ void mma16816(float* c, const u32* a, u32 b0, u32 b1) {
    asm volatile("mma.sync.aligned.m16n8k16.row.col.f32.bf16.bf16.f32 "
        "{%0,%1,%2,%3}, {%4,%5,%6,%7}, {%8,%9}, {%0,%1,%2,%3};"
        : "+f"(c[0]), "+f"(c[1]), "+f"(c[2]), "+f"(c[3])
        : "r"(a[0]), "r"(a[1]), "r"(a[2]), "r"(a[3]), "r"(b0), "r"(b1));
}
__device__ __forceinline__ void ldmx4(u32 addr, u32* r) {
    asm volatile("ldmatrix.sync.aligned.m8n8.x4.shared.b16 {%0,%1,%2,%3}, [%4];"
        : "=r"(r[0]), "=r"(r[1]), "=r"(r[2]), "=r"(r[3]) : "r"(addr));
}
__device__ __forceinline__ u32 s2u(const void* p) {
    u32 a;
    asm("{ .reg .u64 t; cvta.to.shared.u64 t, %1; cvt.u32.u64 %0, t; }" : "=r"(a) : "l"(p));
    return a;
}
__device__ __forceinline__ void cp16(u32 dst, const void* src) {
    asm volatile("cp.async.ca.shared.global [%0], [%1], 16;"
                 :: "r"(dst), "l"(__cvta_generic_to_global(src)));
}
#define CP_COMMIT() asm volatile("cp.async.commit_group;" ::: "memory")
#define CP_WAIT(n)  asm volatile("cp.async.wait_group " #n ";" ::: "memory")

__global__ void __launch_bounds__(512) prepQK(const float4* __restrict__ q,
                                              const float4* __restrict__ k)
{
    int i = blockIdx.x * 512 + threadIdx.x;
    float4 f = q[i];
    f.x *= 0.0625f; f.y *= 0.0625f; f.z *= 0.0625f; f.w *= 0.0625f;
    u32 h0 = cvt2(f.y, f.x), h1 = cvt2(f.w, f.z);
    u32 l0 = cvt2(f.y - __uint_as_float(h0 & 0xffff0000u),
                  f.x - __uint_as_float(h0 << 16));
    u32 l1 = cvt2(f.w - __uint_as_float(h1 & 0xffff0000u),
                  f.z - __uint_as_float(h1 << 16));
    ((uint2*)g_QH)[i] = make_uint2(h0, h1);
    ((uint2*)g_QL)[i] = make_uint2(l0, l1);
    f = k[i];
    h0 = cvt2(f.y, f.x); h1 = cvt2(f.w, f.z);
    l0 = cvt2(f.y - __uint_as_float(h0 & 0xffff0000u),
              f.x - __uint_as_float(h0 << 16));
    l1 = cvt2(f.w - __uint_as_float(h1 & 0xffff0000u),
              f.z - __uint_as_float(h1 << 16));
    ((uint2*)g_KH)[i] = make_uint2(h0, h1);
    ((uint2*)g_KL)[i] = make_uint2(l0, l1);
}

__global__ void __launch_bounds__(256) prepV(const float* __restrict__ v)
{
    int bh = blockIdx.x, kb = blockIdx.y;
    int d = threadIdx.x & 63, kg = threadIdx.x >> 6;
    const float* Vb = v + bh * 65536;
#pragma unroll
    for (int c = 0; c < 4; c++) {
        int k0 = kb * 128 + c * 32 + kg * 8;
        float x[8];
#pragma unroll
        for (int j = 0; j < 8; j++) x[j] = Vb[(k0 + j) * 64 + d] * 0.25f;
        u32 h[4], l[4];
#pragma unroll
        for (int p = 0; p < 4; p++) {
            h[p] = cvt2(x[2*p+1], x[2*p]);
            l[p] = cvt2(x[2*p+1] - __uint_as_float(h[p] & 0xffff0000u),
                        x[2*p]   - __uint_as_float(h[p] << 16));
        }
        int base = bh * 8192 + d * 128 + (k0 >> 3);
        g_VTH[base] = make_uint4(h[0], h[1], h[2], h[3]);
        g_VTL[base] = make_uint4(l[0], l[1], l[2], l[3]);
    }
}

__global__ void __launch_bounds__(NTHR, 2)
attn_regP(float* __restrict__ og)
{
    extern __shared__ u32 sm[];
    float* smf = (float*)sm;
    const int tid  = threadIdx.x;
    const int lane = tid & 31;
    const int wid  = tid >> 5;
    const int g    = lane >> 2;
    const int tq   = lane & 3;
    const int qt   = blockIdx.x;
    const int bh   = blockIdx.y;
    float* Og = og + (size_t)bh * 65536 + (size_t)qt * 1024;
    const u32 smb = s2u(sm);

    for (int i = tid; i < 16 * 68; i += NTHR) smf[O_W + i] = 0.f;

    {   // Q planes (256 cp16) + K chunk 0
        int pl = tid >> 7, rem = tid & 127, row = rem >> 3, seg = rem & 7;
        cp16(smb + (Q_W + pl * 576 + row * 36 + seg * 4) * 4,
             (pl ? g_QL : g_QH) + (size_t)bh * 8192 + (qt * 16 + row) * 8 + seg);
    }
#pragma unroll
    for (int i = 0; i < 4; i++) {
        int idx = i * NTHR + tid, row = idx >> 3, seg = idx & 7;
        int gi = bh * 8192 + row * 8 + seg;
        cp16(smb + (K_W + row * 36 + seg * 4) * 4, g_KH + gi);
        cp16(smb + (K_W + 4608 + row * 36 + seg * 4) * 4, g_KL + gi);
    }
    CP_COMMIT();
    CP_WAIT(0);
    __syncthreads();

    const u32 QHB = smb + Q_W * 4, QLB = QHB + 2304;
    const int aAdr = (lane & 15) * 144 + (lane >> 4) * 16;
    u32 qh[4][4], ql[4][4];
#pragma unroll
    for (int ks = 0; ks < 4; ks++) {
        ldmx4(QHB + aAdr + ks * 32, qh[ks]);
        ldmx4(QLB + aAdr + ks * 32, ql[ks]);
    }

    // ===== GEMM1: 8 chunks x 2 tiles; C stays in registers =====
    // B-frag ldmx4: mats = (tile, k-half): bm=lane>>3 -> tile bm>>1, khalf bm&1
    const int bm = lane >> 3, br = lane & 7;
    const int bAdr0 = (16 * wid + (bm >> 1) * 8 + br) * 144 + (bm & 1) * 16;

    float cc[16][4];
#pragma unroll 1
    for (int c = 0; c < 8; c++) {
        const int buf = c & 1;
        if (c < 7) {
            const int nb = buf ^ 1;
#pragma unroll
            for (int i = 0; i < 4; i++) {
                int idx = i * NTHR + tid, row = idx >> 3, seg = idx & 7;
                int gi = bh * 8192 + ((c + 1) * 128 + row) * 8 + seg;
                cp16(smb + (K_W + nb * 9216 + row * 36 + seg * 4) * 4, g_KH + gi);
                cp16(smb + (K_W + nb * 9216 + 4608 + row * 36 + seg * 4) * 4, g_KL + gi);
            }
            CP_COMMIT();
            CP_WAIT(1);
        } else {
            CP_WAIT(0);
        }
        __syncthreads();
        const u32 KHB = smb + (K_W + buf * 9216) * 4;
        float* c0 = cc[2 * c];
        float* c1 = cc[2 * c + 1];
        c0[0] = c0[1] = c0[2] = c0[3] = 0.f;
        c1[0] = c1[1] = c1[2] = c1[3] = 0.f;
#pragma unroll
        for (int ks = 0; ks < 4; ks++) {
            u32 Bh[4], Bl[4];
            ldmx4(KHB + bAdr0 + ks * 32, Bh);
            ldmx4(KHB + 18432 + bAdr0 + ks * 32, Bl);
            mma16816(c0, qh[ks], Bh[0], Bh[1]);
            mma16816(c0, qh[ks], Bl[0], Bl[1]);
            mma16816(c0, ql[ks], Bh[0], Bh[1]);
            mma16816(c1, qh[ks], Bh[2], Bh[3]);
            mma16816(c1, qh[ks], Bl[2], Bl[3]);
            mma16816(c1, ql[ks], Bh[2], Bh[3]);
        }
        __syncthreads();
    }

    // prefetch V chunk 0 (hidden under entmax)
#pragma unroll
    for (int i = 0; i < 4; i++) {
        int idx = i * NTHR + tid, d = idx >> 4, s = idx & 15;
        int gi = bh * 8192 + d * 128 + s;
        cp16(smb + (K_W + d * 68 + s * 4) * 4, g_VTH + gi);
        cp16(smb + (K_W + 4608 + d * 68 + s * 4) * 4, g_VTL + gi);
    }
    CP_COMMIT();

    // ===== entmax-1.5 Newton, in registers (rows g and g+8) =====
    float mg = -1e30f, mh = -1e30f;
#pragma unroll
    for (int T = 0; T < 16; T++) {
        mg = fmaxf(mg, fmaxf(cc[T][0], cc[T][1]));
        mh = fmaxf(mh, fmaxf(cc[T][2], cc[T][3]));
    }
    mg = fmaxf(mg, __shfl_xor_sync(~0u, mg, 1));
    mg = fmaxf(mg, __shfl_xor_sync(~0u, mg, 2));
    mh = fmaxf(mh, __shfl_xor_sync(~0u, mh, 1));
    mh = fmaxf(mh, __shfl_xor_sync(~0u, mh, 2));
    if (tq == 0) {
        smf[RED_W + (32 + g) * 8 + wid] = mg;
        smf[RED_W + (40 + g) * 8 + wid] = mh;
    }
    __syncthreads();
    float Mg = -1e30f, Mh = -1e30f;
#pragma unroll
    for (int w = 0; w < 8; w++) {
        Mg = fmaxf(Mg, smf[RED_W + (32 + g) * 8 + w]);
        Mh = fmaxf(Mh, smf[RED_W + (40 + g) * 8 + w]);
    }
    float taug = Mg - 1.f, tauh = Mh - 1.f;

    u64 xg[16], xh[16];
#pragma unroll
    for (int T = 0; T < 16; T++) {
        xg[T] = pk64(cc[T][0], cc[T][1]);
        xh[T] = pk64(cc[T][2], cc[T][3]);
    }
    const u64 ABS2 = 0x7fffffff7fffffffULL;
#pragma unroll 1
    for (int it = 0; it < NEWTON; it++) {
        const int p = it & 1;
        u64 ntg = dup2(-taug), nth = dup2(-tauh);
        u64 s2g = 0, r2g = 0, s2h = 0, r2h = 0;
#pragma unroll
        for (int T = 0; T < 16; T++) {
            u64 tg = add2(xg[T], ntg);
            u64 ug = add2(tg, tg & ABS2);        // 2*max(t,0)
            s2g = fma2(ug, ug, s2g); r2g = add2(r2g, ug);
            u64 th = add2(xh[T], nth);
            u64 uh = add2(th, th & ABS2);
            s2h = fma2(uh, uh, s2h); r2h = add2(r2h, uh);
        }
        float2 v2;
        v2 = *(float2*)&s2g; float fsg = v2.x + v2.y;
        v2 = *(float2*)&r2g; float frg = v2.x + v2.y;
        v2 = *(float2*)&s2h; float fsh = v2.x + v2.y;
        v2 = *(float2*)&r2h; float frh = v2.x + v2.y;
        fsg += __shfl_xor_sync(~0u, fsg, 1); fsg += __shfl_xor_sync(~0u, fsg, 2);
        frg += __shfl_xor_sync(~0u, frg, 1); frg += __shfl_xor_sync(~0u, frg, 2);
        fsh += __shfl_xor_sync(~0u, fsh, 1); fsh += __shfl_xor_sync(~0u, fsh, 2);
        frh += __shfl_xor_sync(~0u, frh, 1); frh += __shfl_xor_sync(~0u, frh, 2);
        if (tq == 0) {
            smf[RED_W + (p * 32 + g) * 8 + wid]      = fsg;
            smf[RED_W + (p * 32 + 16 + g) * 8 + wid] = frg;
            smf[RED_W + (p * 32 + 8 + g) * 8 + wid]  = fsh;
            smf[RED_W + (p * 32 + 24 + g) * 8 + wid] = frh;
        }
        __syncthreads();
        float S = 0.f, R = 0.f, Sh = 0.f, Rh = 0.f;
#pragma unroll
        for (int w = 0; w < 8; w++) {
            S  += smf[RED_W + (p * 32 + g) * 8 + w];
            R  += smf[RED_W + (p * 32 + 16 + g) * 8 + w];
            Sh += smf[RED_W + (p * 32 + 8 + g) * 8 + w];
            Rh += smf[RED_W + (p * 32 + 24 + g) * 8 + w];
        }
        taug += __fdividef(S - 4.f, 4.f * R);     // s2 counts 4u^2
        tauh += __fdividef(Sh - 4.f, 4.f * Rh);
    }
    const u64 ntgF = dup2(-taug), nthF = dup2(-tauh);

    // ===== GEMM2: O = P V, fused m16n8k16, P frags from registers =====
    float oc[8][4];
#pragma unroll
    for (int dt = 0; dt < 8; dt++)
        oc[dt][0] = oc[dt][1] = oc[dt][2] = oc[dt][3] = 0.f;

#pragma unroll 1
    for (int c = 0; c < 8; c++) {
        const int buf = c & 1;
        if (c < 7) {
            const int nb = buf ^ 1;
#pragma unroll
            for (int i = 0; i < 4; i++) {
                int idx = i * NTHR + tid, d = idx >> 4, s = idx & 15;
                int gi = bh * 8192 + d * 128 + (c + 1) * 16 + s;
                cp16(smb + (K_W + nb * 9216 + d * 68 + s * 4) * 4, g_VTH + gi);
                cp16(smb + (K_W + nb * 9216 + 4608 + d * 68 + s * 4) * 4, g_VTL + gi);
            }
            CP_COMMIT();
            CP_WAIT(1);
        } else {
            CP_WAIT(0);
        }
        __syncthreads();
        const u32 VHB = smb + (K_W + buf * 9216) * 4;

        // A-frags for both k8 halves straight from registers
        u32 aH[4], aL[4];
#pragma unroll
        for (int kk = 0; kk < 2; kk++) {
            const int T = 2 * c + kk;
            u64 tg = add2(xg[T], ntgF);
            u64 ug = add2(tg, tg & ABS2);
            u64 Pg = mul2(ug, ug);                 // 4p (V carries the /4)
            u64 th = add2(xh[T], nthF);
            u64 uh = add2(th, th & ABS2);
            u64 Ph = mul2(uh, uh);
            float2 pg = *(float2*)&Pg, ph = *(float2*)&Ph;
            u32 h0 = cvt2(pg.y, pg.x);
            u32 h1 = cvt2(ph.y, ph.x);
            aH[2 * kk]     = h0;
            aH[2 * kk + 1] = h1;
            aL[2 * kk]     = cvt2(pg.y - __uint_as_float(h0 & 0xffff0000u),
                                  pg.x - __uint_as_float(h0 << 16));
            aL[2 * kk + 1] = cvt2(ph.y - __uint_as_float(h1 & 0xffff0000u),
                                  ph.x - __uint_as_float(h1 << 16));
        }

        const u32 vA0 = VHB + lane * 272 + (16 * wid) * 2;   // k-half 0
        const u32 vA1 = vA0 + 16;                            // k-half 1
        u32 X0[4], X1[4], Z0[4], Z1[4];
        ldmx4(vA0, X0);            // hi, d 0-31
        ldmx4(vA1, X1);
        ldmx4(vA0 + 18432, Z0);    // lo, d 0-31
        ldmx4(vA1 + 18432, Z1);
#pragma unroll
        for (int dt = 0; dt < 4; dt++) {
            mma16816(oc[dt], aH, X0[dt], X1[dt]);
            mma16816(oc[dt], aH, Z0[dt], Z1[dt]);
            mma16816(oc[dt], aL, X0[dt], X1[dt]);
        }
        ldmx4(vA0 + 8704, X0);             // hi, d 32-63
        ldmx4(vA1 + 8704, X1);
        ldmx4(vA0 + 8704 + 18432, Z0);     // lo, d 32-63
        ldmx4(vA1 + 8704 + 18432, Z1);
#pragma unroll
        for (int dt = 0; dt < 4; dt++) {
            mma16816(oc[dt + 4], aH, X0[dt], X1[dt]);
            mma16816(oc[dt + 4], aH, Z0[dt], Z1[dt]);
            mma16816(oc[dt + 4], aL, X0[dt], X1[dt]);
        }
        __syncthreads();
    }

    // ===== k-split reduction + output =====
#pragma unroll
    for (int dt = 0; dt < 8; dt++) {
        int col = dt * 8 + 2 * tq;
        atomicAdd(&smf[O_W + g * 68 + col],           oc[dt][0]);
        atomicAdd(&smf[O_W + g * 68 + col + 1],       oc[dt][1]);
        atomicAdd(&smf[O_W + (g + 8) * 68 + col],     oc[dt][2]);
        atomicAdd(&smf[O_W + (g + 8) * 68 + col + 1], oc[dt][3]);
    }
    __syncthreads();
#pragma unroll
    for (int i = 0; i < 4; i++) {
        int idx = i * NTHR + tid;
        int q = idx >> 6, d = idx & 63;
        Og[idx] = smf[O_W + q * 68 + d];
    }
}

extern "C" void kernel_launch(void* const* d_in, const int* in_sizes, int n_in,
                              void* d_out, int out_size)
{
    const float* q = (const float*)d_in[0];
    const float* k = (const float*)d_in[1];
    const float* v = (const float*)d_in[2];
    float* out = (float*)d_out;

    cudaFuncSetAttribute(attn_regP,
                         cudaFuncAttributeMaxDynamicSharedMemorySize, SMEM_BYTES);

    prepQK<<<2048, 512>>>((const float4*)q, (const float4*)k);
    prepV<<<dim3(64, 8), 256>>>(v);
    dim3 grid(64, 64);
    attn_regP<<<grid, NTHR, SMEM_BYTES>>>(out);
}

// round 17
// speedup vs baseline: 1.1737x; 1.0751x over previous
#include <cuda_runtime.h>

#define NTHR 256
#define NEWTON 8
typedef unsigned int u32;
typedef unsigned long long u64;

#define Q_W    0          // 2 planes x 16 x 36 w
#define K_W    1152       // 2 buf x 9216 w (K 128x36x2pl / Vt 64x68x2pl)
#define O_W    19584      // 16 x 68 f32
#define RED_W  20672      // 512 w reduction slots
#define TOT_W  21184
#define SMEM_BYTES (TOT_W * 4)   // 84736

__device__ uint4 g_QH[524288], g_QL[524288];
__device__ uint4 g_KH[524288], g_KL[524288];
__device__ uint4 g_VTH[524288], g_VTL[524288];

__device__ __forceinline__ u32 cvt2(float hi, float lo) {
    u32 d; asm("cvt.rn.bf16x2.f32 %0, %1, %2;" : "=r"(d) : "f"(hi), "f"(lo)); return d;
}
__device__ __forceinline__ u64 pk64(float lo, float hi) {
    u64 d; asm("mov.b64 %0, {%1, %2};" : "=l"(d) : "f"(lo), "f"(hi)); return d;
}
__device__ __forceinline__ u64 dup2(float v) {
    u64 d; asm("mov.b64 %0, {%1, %1};" : "=l"(d) : "f"(v)); return d;
}
__device__ __forceinline__ u64 add2(u64 a, u64 b) {
    u64 d; asm("add.rn.f32x2 %0, %1, %2;" : "=l"(d) : "l"(a), "l"(b)); return d;
}
__device__ __forceinline__ u64 mul2(u64 a, u64 b) {
    u64 d; asm("mul.rn.f32x2 %0, %1, %2;" : "=l"(d) : "l"(a), "l"(b)); return d;
}
__device__ __forceinline__ u64 fma2(u64 a, u64 b, u64 c) {
    u64 d; asm("fma.rn.f32x2 %0, %1, %2, %3;" : "=l"(d) : "l"(a), "l"(b), "l"(c)); return d;
}
__device__ __forceinline__ void mma16816(float* c, const u32* a, u32 b0, u32 b1) {
    asm volatile("mma.sync.aligned.m16n8k16.row.col.f32.bf16.bf16.f32 "
        "{%0,%1,%2,%3}, {%4,%5,%6,%7}, {%8,%9}, {%0,%1,%2,%3};"
        : "+f"(c[0]), "+f"(c[1]), "+f"(c[2]), "+f"(c[3])
        : "r"(a[0]), "r"(a[1]), "r"(a[2]), "r"(a[3]), "r"(b0), "r"(b1));
}
__device__ __forceinline__ void ldmx4(u32 addr, u32* r) {
    asm volatile("ldmatrix.sync.aligned.m8n8.x4.shared.b16 {%0,%1,%2,%3}, [%4];"
        : "=r"(r[0]), "=r"(r[1]), "=r"(r[2]), "=r"(r[3]) : "r"(addr));
}
__device__ __forceinline__ u32 s2u(const void* p) {
    u32 a;
    asm("{ .reg .u64 t; cvta.to.shared.u64 t, %1; cvt.u32.u64 %0, t; }" : "=r"(a) : "l"(p));
    return a;
}
__device__ __forceinline__ void cp16(u32 dst, const void* src) {
    asm volatile("cp.async.ca.shared.global [%0], [%1], 16;"
                 :: "r"(dst), "l"(__cvta_generic_to_global(src)));
}
#define CP_COMMIT() asm volatile("cp.async.commit_group;" ::: "memory")
#define CP_WAIT(n)  asm volatile("cp.async.wait_group " #n ";" ::: "memory")

__global__ void __launch_bounds__(512) prepQK(const float4* __restrict__ q,
                                              const float4* __restrict__ k)
{
    int i = blockIdx.x * 512 + threadIdx.x;
    float4 f = q[i];
    f.x *= 0.0625f; f.y *= 0.0625f; f.z *= 0.0625f; f.w *= 0.0625f;
    u32 h0 = cvt2(f.y, f.x), h1 = cvt2(f.w, f.z);
    u32 l0 = cvt2(f.y - __uint_as_float(h0 & 0xffff0000u),
                  f.x - __uint_as_float(h0 << 16));
    u32 l1 = cvt2(f.w - __uint_as_float(h1 & 0xffff0000u),
                  f.z - __uint_as_float(h1 << 16));
    ((uint2*)g_QH)[i] = make_uint2(h0, h1);
    ((uint2*)g_QL)[i] = make_uint2(l0, l1);
    f = k[i];
    h0 = cvt2(f.y, f.x); h1 = cvt2(f.w, f.z);
    l0 = cvt2(f.y - __uint_as_float(h0 & 0xffff0000u),
              f.x - __uint_as_float(h0 << 16));
    l1 = cvt2(f.w - __uint_as_float(h1 & 0xffff0000u),
              f.z - __uint_as_float(h1 << 16));
    ((uint2*)g_KH)[i] = make_uint2(h0, h1);
    ((uint2*)g_KL)[i] = make_uint2(l0, l1);
}

__global__ void __launch_bounds__(256) prepV(const float* __restrict__ v)
{
    int bh = blockIdx.x, kb = blockIdx.y;
    int d = threadIdx.x & 63, kg = threadIdx.x >> 6;
    const float* Vb = v + bh * 65536;
#pragma unroll
    for (int c = 0; c < 4; c++) {
        int k0 = kb * 128 + c * 32 + kg * 8;
        float x[8];
#pragma unroll
        for (int j = 0; j < 8; j++) x[j] = Vb[(k0 + j) * 64 + d] * 0.25f;
        u32 h[4], l[4];
#pragma unroll
        for (int p = 0; p < 4; p++) {
            h[p] = cvt2(x[2*p+1], x[2*p]);
            l[p] = cvt2(x[2*p+1] - __uint_as_float(h[p] & 0xffff0000u),
                        x[2*p]   - __uint_as_float(h[p] << 16));
        }
        int base = bh * 8192 + d * 128 + (k0 >> 3);
        g_VTH[base] = make_uint4(h[0], h[1], h[2], h[3]);
        g_VTL[base] = make_uint4(l[0], l[1], l[2], l[3]);
    }
}

__global__ void __launch_bounds__(NTHR, 2)
attn_regP(float* __restrict__ og)
{
    extern __shared__ u32 sm[];
    float* smf = (float*)sm;
    const int tid  = threadIdx.x;
    const int lane = tid & 31;
    const int wid  = tid >> 5;
    const int g    = lane >> 2;
    const int tq   = lane & 3;
    const int qt   = blockIdx.x;
    const int bh   = blockIdx.y;
    float* Og = og + (size_t)bh * 65536 + (size_t)qt * 1024;
    const u32 smb = s2u(sm);

    for (int i = tid; i < 16 * 68; i += NTHR) smf[O_W + i] = 0.f;

    {   // Q planes (256 cp16) + K chunk 0, one commit group
        int pl = tid >> 7, rem = tid & 127, row = rem >> 3, seg = rem & 7;
        cp16(smb + (Q_W + pl * 576 + row * 36 + seg * 4) * 4,
             (pl ? g_QL : g_QH) + (size_t)bh * 8192 + (qt * 16 + row) * 8 + seg);
    }
#pragma unroll
    for (int i = 0; i < 4; i++) {
        int idx = i * NTHR + tid, row = idx >> 3, seg = idx & 7;
        int gi = bh * 8192 + row * 8 + seg;
        cp16(smb + (K_W + row * 36 + seg * 4) * 4, g_KH + gi);
        cp16(smb + (K_W + 4608 + row * 36 + seg * 4) * 4, g_KL + gi);
    }
    CP_COMMIT();
    CP_WAIT(0);
    __syncthreads();

    const u32 QHB = smb + Q_W * 4, QLB = QHB + 2304;
    const int aAdr = (lane & 15) * 144 + (lane >> 4) * 16;
    u32 qh[4][4], ql[4][4];
#pragma unroll
    for (int ks = 0; ks < 4; ks++) {
        ldmx4(QHB + aAdr + ks * 32, qh[ks]);
        ldmx4(QLB + aAdr + ks * 32, ql[ks]);
    }

    // ===== GEMM1: 8 chunks x 2 tiles; ONE sync per chunk =====
    // order per chunk: wait(data c) -> sync -> prefetch c+1 -> compute c
    const int bm = lane >> 3, br = lane & 7;
    const int bAdr0 = (16 * wid + (bm >> 1) * 8 + br) * 144 + (bm & 1) * 16;

    float cc[16][4];
#pragma unroll 1
    for (int c = 0; c < 8; c++) {
        const int buf = c & 1;
        CP_WAIT(0);
        __syncthreads();
        if (c < 7) {
            const int nb = buf ^ 1;
#pragma unroll
            for (int i = 0; i < 4; i++) {
                int idx = i * NTHR + tid, row = idx >> 3, seg = idx & 7;
                int gi = bh * 8192 + ((c + 1) * 128 + row) * 8 + seg;
                cp16(smb + (K_W + nb * 9216 + row * 36 + seg * 4) * 4, g_KH + gi);
                cp16(smb + (K_W + nb * 9216 + 4608 + row * 36 + seg * 4) * 4, g_KL + gi);
            }
            CP_COMMIT();
        }
        const u32 KHB = smb + (K_W + buf * 9216) * 4;
        float* c0 = cc[2 * c];
        float* c1 = cc[2 * c + 1];
        c0[0] = c0[1] = c0[2] = c0[3] = 0.f;
        c1[0] = c1[1] = c1[2] = c1[3] = 0.f;
#pragma unroll
        for (int ks = 0; ks < 4; ks++) {
            u32 Bh[4], Bl[4];
            ldmx4(KHB + bAdr0 + ks * 32, Bh);
            ldmx4(KHB + 18432 + bAdr0 + ks * 32, Bl);
            mma16816(c0, qh[ks], Bh[0], Bh[1]);
            mma16816(c0, qh[ks], Bl[0], Bl[1]);
            mma16816(c0, ql[ks], Bh[0], Bh[1]);
            mma16816(c1, qh[ks], Bh[2], Bh[3]);
            mma16816(c1, qh[ks], Bl[2], Bl[3]);
            mma16816(c1, ql[ks], Bh[2], Bh[3]);
        }
    }

    // prefetch V chunk 0 into buf0 (buf0 last used at c=6; all warps passed
    // the c=7 top sync, so compute c=6 is CTA-wide done). Hidden under entmax.
#pragma unroll
    for (int i = 0; i < 4; i++) {
        int idx = i * NTHR + tid, d = idx >> 4, s = idx & 15;
        int gi = bh * 8192 + d * 128 + s;
        cp16(smb + (K_W + d * 68 + s * 4) * 4, g_VTH + gi);
        cp16(smb + (K_W + 4608 + d * 68 + s * 4) * 4, g_VTL + gi);
    }
    CP_COMMIT();

    // ===== entmax-1.5 Newton, in registers (rows g and g+8) =====
    float mg = -1e30f, mh = -1e30f;
#pragma unroll
    for (int T = 0; T < 16; T++) {
        mg = fmaxf(mg, fmaxf(cc[T][0], cc[T][1]));
        mh = fmaxf(mh, fmaxf(cc[T][2], cc[T][3]));
    }
    mg = fmaxf(mg, __shfl_xor_sync(~0u, mg, 1));
    mg = fmaxf(mg, __shfl_xor_sync(~0u, mg, 2));
    mh = fmaxf(mh, __shfl_xor_sync(~0u, mh, 1));
    mh = fmaxf(mh, __shfl_xor_sync(~0u, mh, 2));
    if (tq == 0) {
        smf[RED_W + (32 + g) * 8 + wid] = mg;
        smf[RED_W + (40 + g) * 8 + wid] = mh;
    }
    __syncthreads();
    float Mg = -1e30f, Mh = -1e30f;
#pragma unroll
    for (int w = 0; w < 8; w++) {
        Mg = fmaxf(Mg, smf[RED_W + (32 + g) * 8 + w]);
        Mh = fmaxf(Mh, smf[RED_W + (40 + g) * 8 + w]);
    }
    float taug = Mg - 1.f, tauh = Mh - 1.f;

    u64 xg[16], xh[16];
#pragma unroll
    for (int T = 0; T < 16; T++) {
        xg[T] = pk64(cc[T][0], cc[T][1]);
        xh[T] = pk64(cc[T][2], cc[T][3]);
    }
    const u64 ABS2 = 0x7fffffff7fffffffULL;
#pragma unroll 1
    for (int it = 0; it < NEWTON; it++) {
        const int p = it & 1;
        u64 ntg = dup2(-taug), nth = dup2(-tauh);
        u64 s2g = 0, r2g = 0, s2h = 0, r2h = 0;
#pragma unroll
        for (int T = 0; T < 16; T++) {
            u64 tg = add2(xg[T], ntg);
            u64 ug = add2(tg, tg & ABS2);        // 2*max(t,0)
            s2g = fma2(ug, ug, s2g); r2g = add2(r2g, ug);
            u64 th = add2(xh[T], nth);
            u64 uh = add2(th, th & ABS2);
            s2h = fma2(uh, uh, s2h); r2h = add2(r2h, uh);
        }
        float2 v2;
        v2 = *(float2*)&s2g; float fsg = v2.x + v2.y;
        v2 = *(float2*)&r2g; float frg = v2.x + v2.y;
        v2 = *(float2*)&s2h; float fsh = v2.x + v2.y;
        v2 = *(float2*)&r2h; float frh = v2.x + v2.y;
        fsg += __shfl_xor_sync(~0u, fsg, 1); fsg += __shfl_xor_sync(~0u, fsg, 2);
        frg += __shfl_xor_sync(~0u, frg, 1); frg += __shfl_xor_sync(~0u, frg, 2);
        fsh += __shfl_xor_sync(~0u, fsh, 1); fsh += __shfl_xor_sync(~0u, fsh, 2);
        frh += __shfl_xor_sync(~0u, frh, 1); frh += __shfl_xor_sync(~0u, frh, 2);
        if (tq == 0) {
            smf[RED_W + (p * 32 + g) * 8 + wid]      = fsg;
            smf[RED_W + (p * 32 + 16 + g) * 8 + wid] = frg;
            smf[RED_W + (p * 32 + 8 + g) * 8 + wid]  = fsh;
            smf[RED_W + (p * 32 + 24 + g) * 8 + wid] = frh;
        }
        __syncthreads();
        float S = 0.f, R = 0.f, Sh = 0.f, Rh = 0.f;
#pragma unroll
        for (int w = 0; w < 8; w++) {
            S  += smf[RED_W + (p * 32 + g) * 8 + w];
            R  += smf[RED_W + (p * 32 + 16 + g) * 8 + w];
            Sh += smf[RED_W + (p * 32 + 8 + g) * 8 + w];
            Rh += smf[RED_W + (p * 32 + 24 + g) * 8 + w];
        }
        taug += __fdividef(S - 4.f, 4.f * R);     // s2 counts 4u^2
        tauh += __fdividef(Sh - 4.f, 4.f * Rh);
    }
    const u64 ntgF = dup2(-taug), nthF = dup2(-tauh);

    // ===== GEMM2: O = P V, fused m16n8k16, ONE sync per chunk =====
    float oc[8][4];
#pragma unroll
    for (int dt = 0; dt < 8; dt++)
        oc[dt][0] = oc[dt][1] = oc[dt][2] = oc[dt][3] = 0.f;

#pragma unroll 1
    for (int c = 0; c < 8; c++) {
        const int buf = c & 1;
        CP_WAIT(0);
        __syncthreads();
        if (c < 7) {
            const int nb = buf ^ 1;
#pragma unroll
            for (int i = 0; i < 4; i++) {
                int idx = i * NTHR + tid, d = idx >> 4, s = idx & 15;
                int gi = bh * 8192 + d * 128 + (c + 1) * 16 + s;
                cp16(smb + (K_W + nb * 9216 + d * 68 + s * 4) * 4, g_VTH + gi);
                cp16(smb + (K_W + nb * 9216 + 4608 + d * 68 + s * 4) * 4, g_VTL + gi);
            }
            CP_COMMIT();
        }
        const u32 VHB = smb + (K_W + buf * 9216) * 4;

        // A-frags for both k8 halves straight from registers
        u32 aH[4], aL[4];
#pragma unroll
        for (int kk = 0; kk < 2; kk++) {
            const int T = 2 * c + kk;
            u64 tg = add2(xg[T], ntgF);
            u64 ug = add2(tg, tg & ABS2);
            u64 Pg = mul2(ug, ug);                 // 4p (V carries the /4)
            u64 th = add2(xh[T], nthF);
            u64 uh = add2(th, th & ABS2);
            u64 Ph = mul2(uh, uh);
            float2 pg = *(float2*)&Pg, ph = *(float2*)&Ph;
            u32 h0 = cvt2(pg.y, pg.x);
            u32 h1 = cvt2(ph.y, ph.x);
            aH[2 * kk]     = h0;
            aH[2 * kk + 1] = h1;
            aL[2 * kk]     = cvt2(pg.y - __uint_as_float(h0 & 0xffff0000u),
                                  pg.x - __uint_as_float(h0 << 16));
            aL[2 * kk + 1] = cvt2(ph.y - __uint_as_float(h1 & 0xffff0000u),
                                  ph.x - __uint_as_float(h1 << 16));
        }

        const u32 vA0 = VHB + lane * 272 + (16 * wid) * 2;   // k-half 0
        const u32 vA1 = vA0 + 16;                            // k-half 1
        u32 X0[4], X1[4], Z0[4], Z1[4];
        ldmx4(vA0, X0);            // hi, d 0-31
        ldmx4(vA1, X1);
        ldmx4(vA0 + 18432, Z0);    // lo, d 0-31
        ldmx4(vA1 + 18432, Z1);
#pragma unroll
        for (int dt = 0; dt < 4; dt++) {
            mma16816(oc[dt], aH, X0[dt], X1[dt]);
            mma16816(oc[dt], aH, Z0[dt], Z1[dt]);
            mma16816(oc[dt], aL, X0[dt], X1[dt]);
        }
        ldmx4(vA0 + 8704, X0);             // hi, d 32-63
        ldmx4(vA1 + 8704, X1);
        ldmx4(vA0 + 8704 + 18432, Z0);     // lo, d 32-63
        ldmx4(vA1 + 8704 + 18432, Z1);
#pragma unroll
        for (int dt = 0; dt < 4; dt++) {
            mma16816(oc[dt + 4], aH, X0[dt], X1[dt]);
            mma16816(oc[dt + 4], aH, Z0[dt], Z1[dt]);
            mma16816(oc[dt + 4], aL, X0[dt], X1[dt]);
        }
    }

    // ===== k-split reduction + output =====
#pragma unroll
    for (int dt = 0; dt < 8; dt++) {
        int col = dt * 8 + 2 * tq;
        atomicAdd(&smf[O_W + g * 68 + col],           oc[dt][0]);
        atomicAdd(&smf[O_W + g * 68 + col + 1],       oc[dt][1]);
        atomicAdd(&smf[O_W + (g + 8) * 68 + col],     oc[dt][2]);
        atomicAdd(&smf[O_W + (g + 8) * 68 + col + 1], oc[dt][3]);
    }
    __syncthreads();
#pragma unroll
    for (int i = 0; i < 4; i++) {
        int idx = i * NTHR + tid;
        int q = idx >> 6, d = idx & 63;
        Og[idx] = smf[O_W + q * 68 + d];
    }
}

extern "C" void kernel_launch(void* const* d_in, const int* in_sizes, int n_in,
                              void* d_out, int out_size)
{
    const float* q = (const float*)d_in[0];
    const float* k = (const float*)d_in[1];
    const float* v = (const float*)d_in[2];
    float* out = (float*)d_out;

    cudaFuncSetAttribute(attn_regP,
                         cudaFuncAttributeMaxDynamicSharedMemorySize, SMEM_BYTES);

    prepQK<<<2048, 512>>>((const float4*)q, (const float4*)k);
    prepV<<<dim3(64, 8), 256>>>(v);
    dim3 grid(64, 64);
    attn_regP<<<grid, NTHR, SMEM_BYTES>>>(out);
}